// round 1
// baseline (speedup 1.0000x reference)
#include <cuda_runtime.h>
#include <cstdint>

// Problem constants (fixed by reference setup)
#define BB 128          // batch
#define PP 1200         // feature dim
#define SEG 120         // p-segment size (divides 240-block structure)
#define NPB (BB * PP)   // 153600

// Static scratch (no allocations allowed)
__device__ float g_h[2][NPB];         // ping-pong h buffers
__device__ float g_C[NPB];            // frozen-contribution cache C[b,q]
__device__ float g_partial[10 * NPB]; // per-segment partial sums [seg][b][q]

__device__ __forceinline__ float f_p(float x) {
    // LeakyReLU(clamp(x,-1,1)), slope 0.01
    float t = fminf(fmaxf(x, -1.0f), 1.0f);
    return t > 0.0f ? t : 0.01f * t;
}

// 16-byte streaming load as two packed f32x2 (64-bit) registers
struct U64x2 { unsigned long long a, b; };
__device__ __forceinline__ U64x2 ldg_cs_128(const void* p) {
    U64x2 r;
    asm("ld.global.cs.v2.u64 {%0,%1}, [%2];" : "=l"(r.a), "=l"(r.b) : "l"(p));
    return r;
}

// Packed dual-fp32 FMA: acc = m * hp + acc   (Blackwell f32x2 pipe)
#define FMA2(acc, m, hp) \
    asm("fma.rn.f32x2 %0, %1, %2, %0;" : "+l"(acc) : "l"(m), "l"(hp))

// ---------------------------------------------------------------------------
// init: h0 = f_p(query); C = 0
// ---------------------------------------------------------------------------
__global__ void init_kernel(const float* __restrict__ query, float* __restrict__ h0) {
    int i = blockIdx.x * blockDim.x + threadIdx.x;
    if (i < NPB) {
        h0[i] = f_p(query[i]);
        g_C[i] = 0.0f;
    }
}

// ---------------------------------------------------------------------------
// phase A: partial[seg][b][q] = sum_{p in segment} h[b,p] * M[b,p,q],  q < n_on
// Each thread owns 16 consecutive q (4 float4 loads per p).
// h segment is held in smem as duplicated pairs so LDS.64 yields (hp,hp).
// ---------------------------------------------------------------------------
__global__ __launch_bounds__(128) void phaseA(
    const float* __restrict__ hin, const float* __restrict__ M, int n_on)
{
    const int seg = blockIdx.x;
    const int b   = blockIdx.y;
    const int tid = threadIdx.x;

    __shared__ float2 hd[SEG];
    if (tid < SEG) {
        float v = hin[b * PP + seg * SEG + tid];
        hd[tid] = make_float2(v, v);
    }
    __syncthreads();

    const int q0 = tid * 16;
    if (q0 >= n_on) return;

    const char* base = (const char*)(M + (size_t)b * PP * PP
                                       + (size_t)seg * SEG * PP + q0);

    unsigned long long acc0 = 0, acc1 = 0, acc2 = 0, acc3 = 0;
    unsigned long long acc4 = 0, acc5 = 0, acc6 = 0, acc7 = 0;

    #pragma unroll 4
    for (int p = 0; p < SEG; ++p) {
        unsigned long long hp = *reinterpret_cast<const unsigned long long*>(&hd[p]);
        const char* r = base + (size_t)p * (PP * 4);
        U64x2 m0 = ldg_cs_128(r);
        U64x2 m1 = ldg_cs_128(r + 16);
        U64x2 m2 = ldg_cs_128(r + 32);
        U64x2 m3 = ldg_cs_128(r + 48);
        FMA2(acc0, m0.a, hp); FMA2(acc1, m0.b, hp);
        FMA2(acc2, m1.a, hp); FMA2(acc3, m1.b, hp);
        FMA2(acc4, m2.a, hp); FMA2(acc5, m2.b, hp);
        FMA2(acc6, m3.a, hp); FMA2(acc7, m3.b, hp);
    }

    unsigned long long* out = reinterpret_cast<unsigned long long*>(
        g_partial + ((size_t)seg * BB + b) * PP + q0);
    out[0] = acc0; out[1] = acc1; out[2] = acc2; out[3] = acc3;
    out[4] = acc4; out[5] = acc5; out[6] = acc6; out[7] = acc7;
}

// ---------------------------------------------------------------------------
// phase B: mv = C + sum(partials); update h (q < n_on), copy frozen tail;
// fold newly-frozen segment contributions into C.
// ---------------------------------------------------------------------------
__global__ void phaseB(const float* __restrict__ hin, float* __restrict__ hout,
                       int n_on, int nactive, int nsegs)
{
    int i = blockIdx.x * blockDim.x + threadIdx.x;
    if (i >= NPB) return;
    int q = i % PP;
    int b = i / PP;

    float h = hin[i];
    if (q >= n_on) {           // frozen columns: pass through
        hout[i] = h;
        return;
    }

    float sa = 0.0f, sf = 0.0f;
    const float* pp = g_partial + (size_t)b * PP + q;
    #pragma unroll
    for (int s = 0; s < 10; ++s) {
        if (s >= nsegs) break;
        float v = pp[(size_t)s * NPB];
        if (s < nactive) sa += v; else sf += v;
    }

    float c  = g_C[i];
    float mv = sa + sf + c;
    if (nsegs > nactive) g_C[i] = c + sf;   // fold newly-frozen contribution

    // h_new = f_p(kappa*h + h*mv) = f_p(h*(kappa+mv))
    hout[i] = f_p(h * (0.8f + mv));
}

// ---------------------------------------------------------------------------
extern "C" void kernel_launch(void* const* d_in, const int* in_sizes, int n_in,
                              void* d_out, int out_size)
{
    const float* query = (const float*)d_in[0];
    const float* M     = (const float*)d_in[1];
    float*       out   = (float*)d_out;

    float* hbase;
    cudaGetSymbolAddress((void**)&hbase, g_h);

    init_kernel<<<(NPB + 255) / 256, 256>>>(query, hbase);

    const int n_on_arr[5] = {1200, 960, 720, 480, 240};
    int prev = 1200;
    for (int it = 0; it < 5; ++it) {
        int non   = n_on_arr[it];
        int nsegs = prev / SEG;   // p range read this iter: [0, prev)
        int nact  = non  / SEG;   // active p range: [0, non)

        const float* hin = hbase + (it & 1) * NPB;
        float* hout = (it == 4) ? out : hbase + ((it + 1) & 1) * NPB;

        dim3 gA(nsegs, BB);
        phaseA<<<gA, 128>>>(hin, M, non);
        phaseB<<<(NPB + 255) / 256, 256>>>(hin, hout, non, nact, nsegs);

        prev = non;
    }
}

// round 2
// speedup vs baseline: 1.1935x; 1.1935x over previous
#include <cuda_runtime.h>
#include <cstdint>

#define BB 128          // batch
#define PP 1200         // feature dim
#define SEG 240         // p-segment size (aligned to 240-block mask structure)
#define NSEG_MAX 5
#define QT 512          // q-tile width (floats)
#define NPB (BB * PP)   // 153600

// Static scratch (no allocations allowed)
__device__ float g_h[2][NPB];               // ping-pong h buffers
__device__ float g_C[NPB];                  // frozen-contribution cache C[b,q]
__device__ float g_partial[NSEG_MAX * NPB]; // per-segment partial sums [seg][b][q]

__device__ __forceinline__ float f_p(float x) {
    float t = fminf(fmaxf(x, -1.0f), 1.0f);
    return t > 0.0f ? t : 0.01f * t;
}

// 16-byte streaming load as two packed f32x2 (64-bit) registers
struct U64x2 { unsigned long long a, b; };
__device__ __forceinline__ U64x2 ldg_cs_128(const void* p) {
    U64x2 r;
    asm("ld.global.cs.v2.u64 {%0,%1}, [%2];" : "=l"(r.a), "=l"(r.b) : "l"(p));
    return r;
}

// Packed dual-fp32 FMA: acc = m * hp + acc   (Blackwell f32x2 pipe)
#define FMA2(acc, m, hp) \
    asm("fma.rn.f32x2 %0, %1, %2, %0;" : "+l"(acc) : "l"(m), "l"(hp))

// ---------------------------------------------------------------------------
// init: h0 = f_p(query); C = 0
// ---------------------------------------------------------------------------
__global__ void init_kernel(const float* __restrict__ query, float* __restrict__ h0) {
    int i = blockIdx.x * blockDim.x + threadIdx.x;
    if (i < NPB) {
        h0[i] = f_p(query[i]);
        g_C[i] = 0.0f;
    }
}

// ---------------------------------------------------------------------------
// phase A: partial[seg][b][q] = sum_{p in seg} h[b,p] * M[b,p,q]
// Grid: (nsegs, B, qtiles). Thread owns 4 consecutive q -> every warp
// LDG.128 is a contiguous 512B request (fully coalesced, nL=4).
// ---------------------------------------------------------------------------
__global__ __launch_bounds__(128) void phaseA(
    const float* __restrict__ hin, const float* __restrict__ M, int n_on)
{
    const int seg = blockIdx.x;
    const int b   = blockIdx.y;
    const int tid = threadIdx.x;

    __shared__ float2 hd[SEG];
    #pragma unroll
    for (int i = tid; i < SEG; i += 128) {
        float v = hin[b * PP + seg * SEG + i];
        hd[i] = make_float2(v, v);
    }
    __syncthreads();

    const int q0 = blockIdx.z * QT + tid * 4;
    if (q0 >= n_on) return;

    const char* base = (const char*)(M + (size_t)b * PP * PP
                                       + (size_t)seg * SEG * PP + q0);

    unsigned long long acc0 = 0, acc1 = 0;

    #pragma unroll 8
    for (int p = 0; p < SEG; ++p) {
        unsigned long long hp = *reinterpret_cast<const unsigned long long*>(&hd[p]);
        U64x2 m = ldg_cs_128(base + (size_t)p * (PP * 4));
        FMA2(acc0, m.a, hp);
        FMA2(acc1, m.b, hp);
    }

    unsigned long long* out = reinterpret_cast<unsigned long long*>(
        g_partial + ((size_t)seg * BB + b) * PP + q0);
    out[0] = acc0;
    out[1] = acc1;
}

// ---------------------------------------------------------------------------
// phase B: mv = C + sum(partials); update h (q < n_on), copy frozen tail;
// fold newly-frozen segment contributions into C.
// ---------------------------------------------------------------------------
__global__ void phaseB(const float* __restrict__ hin, float* __restrict__ hout,
                       int n_on, int nactive, int nsegs)
{
    int i = blockIdx.x * blockDim.x + threadIdx.x;
    if (i >= NPB) return;
    int q = i % PP;
    int b = i / PP;

    float h = hin[i];
    if (q >= n_on) {           // frozen columns: pass through
        hout[i] = h;
        return;
    }

    float sa = 0.0f, sf = 0.0f;
    const float* pp = g_partial + (size_t)b * PP + q;
    #pragma unroll
    for (int s = 0; s < NSEG_MAX; ++s) {
        if (s >= nsegs) break;
        float v = pp[(size_t)s * NPB];
        if (s < nactive) sa += v; else sf += v;
    }

    float c  = g_C[i];
    float mv = sa + sf + c;
    if (nsegs > nactive) g_C[i] = c + sf;   // fold newly-frozen contribution

    hout[i] = f_p(h * (0.8f + mv));
}

// ---------------------------------------------------------------------------
extern "C" void kernel_launch(void* const* d_in, const int* in_sizes, int n_in,
                              void* d_out, int out_size)
{
    const float* query = (const float*)d_in[0];
    const float* M     = (const float*)d_in[1];
    float*       out   = (float*)d_out;

    float* hbase;
    cudaGetSymbolAddress((void**)&hbase, g_h);

    init_kernel<<<(NPB + 255) / 256, 256>>>(query, hbase);

    const int n_on_arr[5] = {1200, 960, 720, 480, 240};
    int prev = 1200;
    for (int it = 0; it < 5; ++it) {
        int non    = n_on_arr[it];
        int nsegs  = prev / SEG;   // p range read this iter: [0, prev)
        int nact   = non  / SEG;   // active p range: [0, non)
        int qtiles = (non + QT - 1) / QT;

        const float* hin = hbase + (it & 1) * NPB;
        float* hout = (it == 4) ? out : hbase + ((it + 1) & 1) * NPB;

        dim3 gA(nsegs, BB, qtiles);
        phaseA<<<gA, 128>>>(hin, M, non);
        phaseB<<<(NPB + 255) / 256, 256>>>(hin, hout, non, nact, nsegs);

        prev = non;
    }
}